// round 16
// baseline (speedup 1.0000x reference)
#include <cuda_runtime.h>
#include <math.h>
#include <stdint.h>

#define S_LEN   1024
#define BATCH   4
#define NTOK    4096
#define DMODEL  768
#define NHEAD   12
#define HDIM    64
#define D3      2304
#define DFF     3072
#define NLAYER  12
#define VOCAB   50257
#define VPAD    50304       // 128*393

// ---------------- scratch (device globals) ---------------------------------
__device__ float g_x   [NTOK * DMODEL];
__device__ float g_h   [NTOK * DMODEL];
__device__ float g_qkv [NTOK * D3];
__device__ float g_att [NTOK * DMODEL];
__device__ float g_mlp [NTOK * DFF];
__device__ float g_rowsum[NTOK];
// pre-transposed weights, [N,K] K-major, tf32-rounded
__device__ float g_qkvwT[NLAYER * D3 * DMODEL];
__device__ float g_projwT[NLAYER * DMODEL * DMODEL];
__device__ float g_f1wT [NLAYER * DFF * DMODEL];
__device__ float g_f2wT [NLAYER * DMODEL * DFF];
__device__ float g_lmwT [VPAD * DMODEL];

// ---------------- small asm helpers -----------------------------------------
__device__ __forceinline__ uint32_t smem_u32(const void* p) {
    uint32_t a;
    asm("{ .reg .u64 t; cvta.to.shared.u64 t, %1; cvt.u32.u64 %0, t; }"
        : "=r"(a) : "l"(p));
    return a;
}
__device__ __forceinline__ float f2tf32_f(float v) {
    uint32_t r;
    asm("cvt.rna.tf32.f32 %0, %1;" : "=r"(r) : "f"(v));
    return __uint_as_float(r);
}
#define CP_ASYNC16(dst, src) \
    asm volatile("cp.async.cg.shared.global [%0], [%1], 16;" \
                 :: "r"(dst), "l"(src) : "memory")
#define CP_COMMIT() asm volatile("cp.async.commit_group;" ::: "memory")
#define CP_WAIT0()  asm volatile("cp.async.wait_group 0;" ::: "memory")

__device__ __forceinline__ void mma_tf32(float& c0, float& c1, float& c2, float& c3,
                                         uint32_t a0, uint32_t a1, uint32_t a2, uint32_t a3,
                                         uint32_t b0, uint32_t b1) {
    asm volatile(
        "mma.sync.aligned.m16n8k8.row.col.f32.tf32.tf32.f32 "
        "{%0,%1,%2,%3}, {%4,%5,%6,%7}, {%8,%9}, {%0,%1,%2,%3};"
        : "+f"(c0), "+f"(c1), "+f"(c2), "+f"(c3)
        : "r"(a0), "r"(a1), "r"(a2), "r"(a3), "r"(b0), "r"(b1));
}

__device__ __forceinline__ float gelu_exact(float x) {
    return 0.5f * x * (1.f + erff(x * 0.70710678118654752f));
}

// ---------------- tf32 mma.sync GEMM (R11 mainloop; optional CE epilogue) ----
#define SM_STRIDE 36
#define SM_TILE   (128 * SM_STRIDE)
#define GEMM_SMEM (4 * SM_TILE * 4)

template<bool HAS_BIAS, bool DO_GELU, bool HAS_RES, bool ROUND_OUT, bool CE_SUM>
__global__ void __launch_bounds__(256)
mma_gemm(const float* __restrict__ A, const float* __restrict__ BT,
         const float* __restrict__ bias, const float* __restrict__ R,
         float* __restrict__ C, int M, int N, int K, int ldc,
         float* __restrict__ rowsum)
{
    extern __shared__ float sm[];
    float* As = sm;                  // [2][128][36]
    float* Bs = sm + 2 * SM_TILE;    // [2][128][36]
    __shared__ float rs[128];        // CE row partial sums (only used if CE_SUM)

    const int tid = threadIdx.x;
    const int wid = tid >> 5, lid = tid & 31;
    const int wm = wid >> 2;
    const int wn = wid & 3;
    const int g  = lid >> 2;
    const int tq = lid & 3;

    const int m0 = blockIdx.x * 128;
    const int n0 = blockIdx.y * 128;

    const int arow  = tid >> 1;
    const int ahalf = (tid & 1) * 16;

    const uint32_t sA[2] = { smem_u32(As), smem_u32(As + SM_TILE) };
    const uint32_t sB[2] = { smem_u32(Bs), smem_u32(Bs + SM_TILE) };
    const uint32_t rowoff = (uint32_t)(arow * SM_STRIDE + ahalf) * 4u;

    const float* Agp = A  + (size_t)(m0 + arow) * K + ahalf;
    const float* Bgp = BT + (size_t)(n0 + arow) * K + ahalf;

    if (CE_SUM) {
        if (tid < 128) rs[tid] = 0.f;
    }

    float acc[4][4][4];
    #pragma unroll
    for (int i = 0; i < 4; i++)
        #pragma unroll
        for (int j = 0; j < 4; j++)
            #pragma unroll
            for (int q = 0; q < 4; q++) acc[i][j][q] = 0.f;

    const int nk = K >> 5;

    #pragma unroll
    for (int q = 0; q < 4; q++) {
        CP_ASYNC16(sA[0] + rowoff + q * 16u, Agp + q * 4);
        CP_ASYNC16(sB[0] + rowoff + q * 16u, Bgp + q * 4);
    }
    CP_COMMIT();
    CP_WAIT0();
    __syncthreads();

    for (int kb = 0; kb < nk; kb++) {
        const int buf = kb & 1;
        if (kb + 1 < nk) {
            const float* ap = Agp + (size_t)(kb + 1) * 32;
            const float* bp = Bgp + (size_t)(kb + 1) * 32;
            #pragma unroll
            for (int q = 0; q < 4; q++) {
                CP_ASYNC16(sA[buf ^ 1] + rowoff + q * 16u, ap + q * 4);
                CP_ASYNC16(sB[buf ^ 1] + rowoff + q * 16u, bp + q * 4);
            }
            CP_COMMIT();
        }

        const uint32_t* Ab = (const uint32_t*)(As + buf * SM_TILE);
        const uint32_t* Bb = (const uint32_t*)(Bs + buf * SM_TILE);

        #pragma unroll
        for (int ks = 0; ks < 4; ks++) {
            const int k0 = ks * 8;
            uint32_t af[4][4], bf[4][2];
            #pragma unroll
            for (int mt = 0; mt < 4; mt++) {
                const uint32_t* base = Ab + (wm * 64 + mt * 16 + g) * SM_STRIDE + k0 + tq;
                af[mt][0] = base[0];
                af[mt][1] = base[8 * SM_STRIDE];
                af[mt][2] = base[4];
                af[mt][3] = base[8 * SM_STRIDE + 4];
            }
            #pragma unroll
            for (int nt = 0; nt < 4; nt++) {
                const uint32_t* base = Bb + (wn * 32 + nt * 8 + g) * SM_STRIDE + k0 + tq;
                bf[nt][0] = base[0];
                bf[nt][1] = base[4];
            }
            #pragma unroll
            for (int mt = 0; mt < 4; mt++)
                #pragma unroll
                for (int nt = 0; nt < 4; nt++)
                    mma_tf32(acc[mt][nt][0], acc[mt][nt][1], acc[mt][nt][2], acc[mt][nt][3],
                             af[mt][0], af[mt][1], af[mt][2], af[mt][3],
                             bf[nt][0], bf[nt][1]);
        }

        if (kb + 1 < nk) {
            CP_WAIT0();
            __syncthreads();
        }
    }

    const bool vec_ok = ((ldc & 1) == 0);
    float es[4][2];
    if (CE_SUM) {
        #pragma unroll
        for (int mt = 0; mt < 4; mt++) { es[mt][0] = 0.f; es[mt][1] = 0.f; }
    }
    #pragma unroll
    for (int mt = 0; mt < 4; mt++) {
        #pragma unroll
        for (int nt = 0; nt < 4; nt++) {
            const int mrow0 = m0 + wm * 64 + mt * 16 + g;
            const int ncol  = n0 + wn * 32 + nt * 8 + 2 * tq;
            #pragma unroll
            for (int half = 0; half < 2; half++) {
                const int m = mrow0 + half * 8;
                float v0 = acc[mt][nt][half * 2 + 0];
                float v1 = acc[mt][nt][half * 2 + 1];
                if (HAS_BIAS) { v0 += bias[ncol]; v1 += bias[ncol + 1]; }
                if (DO_GELU)  { v0 = gelu_exact(v0); v1 = gelu_exact(v1); }
                if (HAS_RES) {
                    v0 += R[(size_t)m * ldc + ncol];
                    v1 += R[(size_t)m * ldc + ncol + 1];
                }
                if (ROUND_OUT) { v0 = f2tf32_f(v0); v1 = f2tf32_f(v1); }
                if (CE_SUM) {
                    float e = 0.f;
                    if (ncol < N)     e += __expf(v0);
                    if (ncol + 1 < N) e += __expf(v1);
                    es[mt][half] += e;
                }
                float* cp = C + (size_t)m * ldc + ncol;
                if (vec_ok && (ncol + 1 < N)) {
                    *(float2*)cp = make_float2(v0, v1);
                } else {
                    if (ncol < N)     cp[0] = v0;
                    if (ncol + 1 < N) cp[1] = v1;
                }
            }
        }
    }
    if (CE_SUM) {
        __syncthreads();
        #pragma unroll
        for (int mt = 0; mt < 4; mt++) {
            atomicAdd(&rs[wm * 64 + mt * 16 + g],     es[mt][0]);
            atomicAdd(&rs[wm * 64 + mt * 16 + g + 8], es[mt][1]);
        }
        __syncthreads();
        if (tid < 128) atomicAdd(&rowsum[m0 + tid], rs[tid]);
    }
}

// ---------------- weight transpose [K,N] -> [NPAD,K], tf32-rounded ----------
__global__ void __launch_bounds__(256)
transpose_kernel(const float* __restrict__ in, float* __restrict__ out,
                 int K, int N, int NPAD)
{
    __shared__ float t[32][33];
    const int k0 = blockIdx.x * 32, n0 = blockIdx.y * 32;
    const float* ip = in  + (size_t)blockIdx.z * K * N;
    float* op       = out + (size_t)blockIdx.z * NPAD * K;
    const int x = threadIdx.x & 31, y = threadIdx.x >> 5;
    #pragma unroll
    for (int i = y; i < 32; i += 8) {
        int n = n0 + x;
        t[i][x] = (n < N) ? f2tf32_f(ip[(size_t)(k0 + i) * N + n]) : 0.f;
    }
    __syncthreads();
    #pragma unroll
    for (int i = y; i < 32; i += 8) {
        int n = n0 + i;
        if (n < NPAD) op[(size_t)n * K + k0 + x] = t[x][i];
    }
}

// ---------------- block reduce (used by ce_final) ----------------------------
__device__ __forceinline__ float blockReduceSum(float v) {
    __shared__ float sh[32];
    int lane = threadIdx.x & 31, wid = threadIdx.x >> 5;
    #pragma unroll
    for (int o = 16; o; o >>= 1) v += __shfl_xor_sync(0xffffffffu, v, o);
    if (lane == 0) sh[wid] = v;
    __syncthreads();
    if (wid == 0) {
        v = (lane < (int)(blockDim.x >> 5)) ? sh[lane] : 0.f;
        #pragma unroll
        for (int o = 16; o; o >>= 1) v += __shfl_xor_sync(0xffffffffu, v, o);
        if (lane == 0) sh[0] = v;
    }
    __syncthreads();
    float r = sh[0];
    __syncthreads();
    return r;
}

// ---------------- embedding / LN -------------------------------------------
__global__ void embed_kernel(const int* __restrict__ idx,
                             const float* __restrict__ wte,
                             const float* __restrict__ wpe,
                             float* __restrict__ x) {
    int t = blockIdx.x;
    int pos = t & (S_LEN - 1);
    int tok = idx[t];
    const float* we = wte + (size_t)tok * DMODEL;
    const float* pe = wpe + (size_t)pos * DMODEL;
    float* xr = x + (size_t)t * DMODEL;
    for (int d = threadIdx.x; d < DMODEL; d += blockDim.x)
        xr[d] = we[d] + pe[d];
}

// warp-per-row LN: 8 rows/block, shfl-only reductions, float4 I/O.
__global__ void __launch_bounds__(256) ln_kernel(const float* __restrict__ x,
                                                 const float* __restrict__ w,
                                                 const float* __restrict__ b,
                                                 float* __restrict__ y) {
    const int warp = threadIdx.x >> 5, lane = threadIdx.x & 31;
    const int r = blockIdx.x * 8 + warp;
    const float4* xr = (const float4*)(x + (size_t)r * DMODEL);
    float4 v[6];
    float s = 0.f;
    #pragma unroll
    for (int j = 0; j < 6; j++) {
        v[j] = xr[lane + 32 * j];
        s += v[j].x + v[j].y + v[j].z + v[j].w;
    }
    #pragma unroll
    for (int o = 16; o; o >>= 1) s += __shfl_xor_sync(0xffffffffu, s, o);
    const float mean = s * (1.f / DMODEL);
    float vs = 0.f;
    #pragma unroll
    for (int j = 0; j < 6; j++) {
        float dx = v[j].x - mean, dy = v[j].y - mean, dz = v[j].z - mean, dw = v[j].w - mean;
        vs += dx * dx + dy * dy + dz * dz + dw * dw;
    }
    #pragma unroll
    for (int o = 16; o; o >>= 1) vs += __shfl_xor_sync(0xffffffffu, vs, o);
    const float rstd = rsqrtf(vs * (1.f / DMODEL) + 1e-5f);
    const float4* wv = (const float4*)w;
    const float4* bv = (const float4*)b;
    float4* yr = (float4*)(y + (size_t)r * DMODEL);
    #pragma unroll
    for (int j = 0; j < 6; j++) {
        const int c = lane + 32 * j;
        float4 ww = wv[c], bb = bv[c];
        float4 o4;
        o4.x = f2tf32_f((v[j].x - mean) * rstd * ww.x + bb.x);
        o4.y = f2tf32_f((v[j].y - mean) * rstd * ww.y + bb.y);
        o4.z = f2tf32_f((v[j].z - mean) * rstd * ww.z + bb.z);
        o4.w = f2tf32_f((v[j].w - mean) * rstd * ww.w + bb.w);
        yr[c] = o4;
    }
}

// ---------------- flash attention (fp32, causal; 128-row Q tiles) ------------
// 512 threads; Q tile 128 rows, K/V tiles 64 keys; per-thread 4 rows x 4 cols.
// Smem: Qs[128][68], Ks[64][68](KsT d-major), Vs[64][68], Ps[128][68] = 104448 B.
#define AST 68
#define ATT_SMEM ((128 + 64 + 64 + 128) * AST * 4)

__global__ void __launch_bounds__(512) attn_kernel(const float* __restrict__ qkv,
                                                   float* __restrict__ out) {
    extern __shared__ float smf[];
    float* Qs  = smf;                  // [128][AST] row-major
    float* KsT = Qs  + 128 * AST;      // [64 d][AST keys] transposed
    float* Vs  = KsT + 64 * AST;       // [64][AST] row-major
    float* Ps  = Vs  + 64 * AST;       // [128][AST] row-major

    const int b = blockIdx.z, h = blockIdx.y, qb = blockIdx.x;
    const int q0 = qb * 128;
    const int t = threadIdx.x;
    const int tx = t & 15, ty = t >> 4;      // ty: 0..31 -> rows ty*4..ty*4+3
    const float scale = 0.125f;

    // load Q tile (128 rows x 16 float4)
    for (int i = t; i < 128 * 16; i += 512) {
        int r = i >> 4, d4 = (i & 15) * 4;
        float4 q4 = *(const float4*)(qkv + (size_t)(b * S_LEN + q0 + r) * D3 + h * HDIM + d4);
        *(float4*)&Qs[r * AST + d4] = q4;
    }

    float m[4], l[4], o[4][4];
    #pragma unroll
    for (int i = 0; i < 4; i++) {
        m[i] = -3.0e38f; l[i] = 0.f;
        #pragma unroll
        for (int j = 0; j < 4; j++) o[i][j] = 0.f;
    }

    const int nkt = 2 * qb + 2;          // k-tiles covering keys [0, q0+128)
    for (int kt = 0; kt < nkt; kt++) {
        const int k0r = kt * 64;
        __syncthreads();   // prior KsT/Vs reads done; covers Q load on kt==0
        for (int i = t; i < 64 * 16; i += 512) {
            int r = i >> 4, d4 = (i & 15) * 4;
            size_t row = (size_t)(b * S_LEN + k0r + r) * D3 + h * HDIM + d4;
            float4 k4 = *(const float4*)(qkv + row + DMODEL);
            float4 v4 = *(const float4*)(qkv + row + 2 * DMODEL);
            KsT[(d4 + 0) * AST + r] = k4.x;
            KsT[(d4 + 1) * AST + r] = k4.y;
            KsT[(d4 + 2) * AST + r] = k4.z;
            KsT[(d4 + 3) * AST + r] = k4.w;
            *(float4*)&Vs[r * AST + d4] = v4;
        }
        __syncthreads();

        // S = Q K^T * scale
        float s[4][4];
        #pragma unroll
        for (int i = 0; i < 4; i++)
            #pragma unroll
            for (int j = 0; j < 4; j++) s[i][j] = 0.f;
        for (int d0 = 0; d0 < 64; d0 += 4) {
            float4 qv[4], kv[4];
            #pragma unroll
            for (int i = 0; i < 4; i++) qv[i] = *(float4*)&Qs[(ty * 4 + i) * AST + d0];
            #pragma unroll
            for (int dd = 0; dd < 4; dd++) kv[dd] = *(float4*)&KsT[(d0 + dd) * AST + tx * 4];
            #pragma unroll
            for (int i = 0; i < 4; i++) {
                const float qa[4] = {qv[i].x, qv[i].y, qv[i].z, qv[i].w};
                #pragma unroll
                for (int dd = 0; dd < 4; dd++) {
                    s[i][0] = fmaf(qa[dd], kv[dd].x, s[i][0]);
                    s[i][1] = fmaf(qa[dd], kv[dd].y, s[i][1]);
                    s[i][2] = fmaf(qa[dd], kv[dd].z, s[i][2]);
                    s[i][3] = fmaf(qa[dd], kv[dd].w, s[i][3]);
                }
            }
        }
        const int keyoff = k0r - q0;     // key_local = keyoff + tx*4+j vs row ty*4+i
        const bool need_mask = (kt >= 2 * qb);
        #pragma unroll
        for (int i = 0; i < 4; i++)
            #pragma unroll
            for (int j = 0; j < 4; j++) {
                s[i][j] *= scale;
                if (need_mask && (keyoff + tx * 4 + j) > (ty * 4 + i)) s[i][j] = -1.0e30f;
            }

        // online softmax (rows replicated across 16 tx lanes)
        float p[4][4];
        #pragma unroll
        for (int i = 0; i < 4; i++) {
            float mt = fmaxf(fmaxf(s[i][0], s[i][1]), fmaxf(s[i][2], s[i][3]));
            #pragma unroll
            for (int off = 8; off; off >>= 1)
                mt = fmaxf(mt, __shfl_xor_sync(0xffffffffu, mt, off, 16));
            float mn = fmaxf(m[i], mt);
            float alpha = __expf(m[i] - mn);
            float ps = 0.f;
            #pragma unroll
            for (int j = 0; j < 4; j++) { p[i][j] = __expf(s[i][j] - mn); ps += p[i][j]; }
            #pragma unroll
            for (int off = 8; off; off >>= 1)
                ps += __shfl_xor_sync(0xffffffffu, ps, off, 16);
            l[i] = l[i] * alpha + ps;
            m[i] = mn;
            #pragma unroll
            for (int j = 0; j < 4; j++) o[i][j] *= alpha;
        }

        // stage P (rows private to this 16-lane tx group -> warp sync suffices)
        #pragma unroll
        for (int i = 0; i < 4; i++)
            *(float4*)&Ps[(ty * 4 + i) * AST + tx * 4] = make_float4(p[i][0], p[i][1], p[i][2], p[i][3]);
        __syncwarp();

        // O += P @ V
        for (int k0 = 0; k0 < 64; k0 += 4) {
            float4 pv[4], vv[4];
            #pragma unroll
            for (int i = 0; i < 4; i++) pv[i] = *(float4*)&Ps[(ty * 4 + i) * AST + k0];
            #pragma unroll
            for (int kk = 0; kk < 4; kk++) vv[kk] = *(float4*)&Vs[(k0 + kk) * AST + tx * 4];
            #pragma unroll
            for (int i = 0; i < 4; i++) {
                const float pa[4] = {pv[i].x, pv[i].y, pv[i].z, pv[i].w};
                #pragma unroll
                for (int kk = 0; kk < 4; kk++) {
                    o[i][0] = fmaf(pa[kk], vv[kk].x, o[i][0]);
                    o[i][1] = fmaf(pa[kk], vv[kk].y, o[i][1]);
                    o[i][2] = fmaf(pa[kk], vv[kk].z, o[i][2]);
                    o[i][3] = fmaf(pa[kk], vv[kk].w, o[i][3]);
                }
            }
        }
        __syncwarp();   // P reads done before next iteration overwrites
    }

    // output feeds proj GEMM as A -> tf32-round
    #pragma unroll
    for (int i = 0; i < 4; i++) {
        float inv = 1.f / l[i];
        float4 ov = make_float4(f2tf32_f(o[i][0] * inv), f2tf32_f(o[i][1] * inv),
                                f2tf32_f(o[i][2] * inv), f2tf32_f(o[i][3] * inv));
        *(float4*)(out + (size_t)(b * S_LEN + q0 + ty * 4 + i) * DMODEL + h * HDIM + tx * 4) = ov;
    }
}

// ---------------- CE final: loss = mean( log(rowsum) - logit[label] ) -------
__global__ void __launch_bounds__(256) ce_final_kernel(const float* __restrict__ rowsum,
                                                       const float* __restrict__ logits,
                                                       const int* __restrict__ labels,
                                                       float* __restrict__ out) {
    float s = 0.f;
    for (int r = threadIdx.x; r < NTOK; r += 256)
        s += logf(rowsum[r]) - logits[(size_t)r * VOCAB + labels[r]];
    s = blockReduceSum(s);
    if (threadIdx.x == 0) out[0] = s * (1.f / NTOK);
}

// ---------------- host launcher ----------------------------------------------
extern "C" void kernel_launch(void* const* d_in, const int* in_sizes, int n_in,
                              void* d_out, int out_size) {
    const int*   idx   = (const int*)  d_in[0];
    const int*   preds = (const int*)  d_in[1];
    const float* wte   = (const float*)d_in[2];
    const float* wpe   = (const float*)d_in[3];
    const float* ln1w  = (const float*)d_in[4];
    const float* ln1b  = (const float*)d_in[5];
    const float* qkvw  = (const float*)d_in[6];
    const float* qkvb  = (const float*)d_in[7];
    const float* projw = (const float*)d_in[8];
    const float* projb = (const float*)d_in[9];
    const float* ln2w  = (const float*)d_in[10];
    const float* ln2b  = (const float*)d_in[11];
    const float* f1w   = (const float*)d_in[12];
    const float* f1b   = (const float*)d_in[13];
    const float* f2w   = (const float*)d_in[14];
    const float* f2b   = (const float*)d_in[15];
    const float* lnfw  = (const float*)d_in[16];
    const float* lnfb  = (const float*)d_in[17];
    const float* lmw   = (const float*)d_in[18];
    float* out = (float*)d_out;

    float *x, *h, *qkv, *att, *mlp, *rowsum;
    float *qkvwT, *projwT, *f1wT, *f2wT, *lmwT;
    cudaGetSymbolAddress((void**)&x,   g_x);
    cudaGetSymbolAddress((void**)&h,   g_h);
    cudaGetSymbolAddress((void**)&qkv, g_qkv);
    cudaGetSymbolAddress((void**)&att, g_att);
    cudaGetSymbolAddress((void**)&mlp, g_mlp);
    cudaGetSymbolAddress((void**)&rowsum, g_rowsum);
    cudaGetSymbolAddress((void**)&qkvwT, g_qkvwT);
    cudaGetSymbolAddress((void**)&projwT, g_projwT);
    cudaGetSymbolAddress((void**)&f1wT, g_f1wT);
    cudaGetSymbolAddress((void**)&f2wT, g_f2wT);
    cudaGetSymbolAddress((void**)&lmwT, g_lmwT);

    cudaFuncSetAttribute(attn_kernel, cudaFuncAttributeMaxDynamicSharedMemorySize, ATT_SMEM);
    cudaFuncSetAttribute(mma_gemm<true, false, false, false, false>, cudaFuncAttributeMaxDynamicSharedMemorySize, GEMM_SMEM);
    cudaFuncSetAttribute(mma_gemm<true, false, true,  false, false>, cudaFuncAttributeMaxDynamicSharedMemorySize, GEMM_SMEM);
    cudaFuncSetAttribute(mma_gemm<true, true,  false, true,  false>, cudaFuncAttributeMaxDynamicSharedMemorySize, GEMM_SMEM);
    cudaFuncSetAttribute(mma_gemm<false, false, false, false, true>, cudaFuncAttributeMaxDynamicSharedMemorySize, GEMM_SMEM);

    // Launch order keeps the first mma_gemm at launch index 3 (ncu -s window).
    transpose_kernel<<<dim3(DMODEL / 32, D3 / 32, NLAYER), 256>>>(qkvw, qkvwT, DMODEL, D3, D3);
    embed_kernel<<<NTOK, 256>>>(idx, wte, wpe, x);
    ln_kernel<<<NTOK / 8, 256>>>(x, ln1w, ln1b, h);
    mma_gemm<true, false, false, false, false><<<dim3(NTOK / 128, D3 / 128), 256, GEMM_SMEM>>>(
        h, qkvwT, qkvb, nullptr, qkv, NTOK, D3, DMODEL, D3, nullptr);

    transpose_kernel<<<dim3(DMODEL / 32, DMODEL / 32, NLAYER), 256>>>(projw, projwT, DMODEL, DMODEL, DMODEL);
    transpose_kernel<<<dim3(DMODEL / 32, DFF / 32, NLAYER), 256>>>(f1w, f1wT, DMODEL, DFF, DFF);
    transpose_kernel<<<dim3(DFF / 32, DMODEL / 32, NLAYER), 256>>>(f2w, f2wT, DFF, DMODEL, DMODEL);
    transpose_kernel<<<dim3(DMODEL / 32, VPAD / 32, 1), 256>>>(lmw, lmwT, DMODEL, VOCAB, VPAD);
    cudaMemsetAsync(rowsum, 0, NTOK * sizeof(float));

    for (int l = 0; l < NLAYER; l++) {
        if (l > 0) {
            ln_kernel<<<NTOK / 8, 256>>>(x, ln1w + (size_t)l * DMODEL, ln1b + (size_t)l * DMODEL, h);
            mma_gemm<true, false, false, false, false><<<dim3(NTOK / 128, D3 / 128), 256, GEMM_SMEM>>>(
                h, qkvwT + (size_t)l * D3 * DMODEL, qkvb + (size_t)l * D3,
                nullptr, qkv, NTOK, D3, DMODEL, D3, nullptr);
        }

        attn_kernel<<<dim3(S_LEN / 128, NHEAD, BATCH), 512, ATT_SMEM>>>(qkv, att);

        mma_gemm<true, false, true, false, false><<<dim3(NTOK / 128, DMODEL / 128), 256, GEMM_SMEM>>>(
            att, projwT + (size_t)l * DMODEL * DMODEL, projb + (size_t)l * DMODEL,
            x, x, NTOK, DMODEL, DMODEL, DMODEL, nullptr);

        ln_kernel<<<NTOK / 8, 256>>>(x, ln2w + (size_t)l * DMODEL, ln2b + (size_t)l * DMODEL, h);

        mma_gemm<true, true, false, true, false><<<dim3(NTOK / 128, DFF / 128), 256, GEMM_SMEM>>>(
            h, f1wT + (size_t)l * DFF * DMODEL, f1b + (size_t)l * DFF,
            nullptr, mlp, NTOK, DFF, DMODEL, DFF, nullptr);

        mma_gemm<true, false, true, false, false><<<dim3(NTOK / 128, DMODEL / 128), 256, GEMM_SMEM>>>(
            mlp, f2wT + (size_t)l * DMODEL * DFF, f2b + (size_t)l * DMODEL,
            x, x, NTOK, DMODEL, DFF, DMODEL, nullptr);
    }

    ln_kernel<<<NTOK / 8, 256>>>(x, lnfw, lnfb, h);

    mma_gemm<false, false, false, false, true><<<dim3(NTOK / 128, VPAD / 128), 256, GEMM_SMEM>>>(
        h, lmwT, nullptr, nullptr, out, NTOK, VOCAB, DMODEL, VOCAB, rowsum);

    ce_final_kernel<<<1, 256>>>(rowsum, out, preds, out + (size_t)NTOK * VOCAB);
}

// round 17
// speedup vs baseline: 1.0450x; 1.0450x over previous
#include <cuda_runtime.h>
#include <math.h>
#include <stdint.h>

#define S_LEN   1024
#define BATCH   4
#define NTOK    4096
#define DMODEL  768
#define NHEAD   12
#define HDIM    64
#define D3      2304
#define DFF     3072
#define NLAYER  12
#define VOCAB   50257
#define VPAD    50304       // 128*393

// ---------------- scratch (device globals) ---------------------------------
__device__ float g_x   [NTOK * DMODEL];
__device__ float g_h   [NTOK * DMODEL];
__device__ float g_qkv [NTOK * D3];
__device__ float g_att [NTOK * DMODEL];
__device__ float g_mlp [NTOK * DFF];
__device__ float g_rowsum[NTOK];
// pre-transposed weights, [N,K] K-major, tf32-rounded
__device__ float g_qkvwT[NLAYER * D3 * DMODEL];
__device__ float g_projwT[NLAYER * DMODEL * DMODEL];
__device__ float g_f1wT [NLAYER * DFF * DMODEL];
__device__ float g_f2wT [NLAYER * DMODEL * DFF];
__device__ float g_lmwT [VPAD * DMODEL];

// ---------------- small asm helpers -----------------------------------------
__device__ __forceinline__ uint32_t smem_u32(const void* p) {
    uint32_t a;
    asm("{ .reg .u64 t; cvta.to.shared.u64 t, %1; cvt.u32.u64 %0, t; }"
        : "=r"(a) : "l"(p));
    return a;
}
__device__ __forceinline__ float f2tf32_f(float v) {
    uint32_t r;
    asm("cvt.rna.tf32.f32 %0, %1;" : "=r"(r) : "f"(v));
    return __uint_as_float(r);
}
#define CP_ASYNC16(dst, src) \
    asm volatile("cp.async.cg.shared.global [%0], [%1], 16;" \
                 :: "r"(dst), "l"(src) : "memory")
#define CP_COMMIT() asm volatile("cp.async.commit_group;" ::: "memory")
#define CP_WAIT0()  asm volatile("cp.async.wait_group 0;" ::: "memory")

__device__ __forceinline__ void mma_tf32(float& c0, float& c1, float& c2, float& c3,
                                         uint32_t a0, uint32_t a1, uint32_t a2, uint32_t a3,
                                         uint32_t b0, uint32_t b1) {
    asm volatile(
        "mma.sync.aligned.m16n8k8.row.col.f32.tf32.tf32.f32 "
        "{%0,%1,%2,%3}, {%4,%5,%6,%7}, {%8,%9}, {%0,%1,%2,%3};"
        : "+f"(c0), "+f"(c1), "+f"(c2), "+f"(c3)
        : "r"(a0), "r"(a1), "r"(a2), "r"(a3), "r"(b0), "r"(b1));
}

__device__ __forceinline__ float gelu_exact(float x) {
    return 0.5f * x * (1.f + erff(x * 0.70710678118654752f));
}

// ---------------- tf32 mma.sync GEMM (R11 mainloop; optional CE epilogue) ----
#define SM_STRIDE 36
#define SM_TILE   (128 * SM_STRIDE)
#define GEMM_SMEM (4 * SM_TILE * 4)

template<bool HAS_BIAS, bool DO_GELU, bool HAS_RES, bool ROUND_OUT, bool CE_SUM>
__global__ void __launch_bounds__(256)
mma_gemm(const float* __restrict__ A, const float* __restrict__ BT,
         const float* __restrict__ bias, const float* __restrict__ R,
         float* __restrict__ C, int M, int N, int K, int ldc,
         float* __restrict__ rowsum)
{
    extern __shared__ float sm[];
    float* As = sm;                  // [2][128][36]
    float* Bs = sm + 2 * SM_TILE;    // [2][128][36]
    __shared__ float rs[128];        // CE row partial sums (only used if CE_SUM)

    const int tid = threadIdx.x;
    const int wid = tid >> 5, lid = tid & 31;
    const int wm = wid >> 2;
    const int wn = wid & 3;
    const int g  = lid >> 2;
    const int tq = lid & 3;

    const int m0 = blockIdx.x * 128;
    const int n0 = blockIdx.y * 128;

    const int arow  = tid >> 1;
    const int ahalf = (tid & 1) * 16;

    const uint32_t sA[2] = { smem_u32(As), smem_u32(As + SM_TILE) };
    const uint32_t sB[2] = { smem_u32(Bs), smem_u32(Bs + SM_TILE) };
    const uint32_t rowoff = (uint32_t)(arow * SM_STRIDE + ahalf) * 4u;

    const float* Agp = A  + (size_t)(m0 + arow) * K + ahalf;
    const float* Bgp = BT + (size_t)(n0 + arow) * K + ahalf;

    if (CE_SUM) {
        if (tid < 128) rs[tid] = 0.f;
    }

    float acc[4][4][4];
    #pragma unroll
    for (int i = 0; i < 4; i++)
        #pragma unroll
        for (int j = 0; j < 4; j++)
            #pragma unroll
            for (int q = 0; q < 4; q++) acc[i][j][q] = 0.f;

    const int nk = K >> 5;

    #pragma unroll
    for (int q = 0; q < 4; q++) {
        CP_ASYNC16(sA[0] + rowoff + q * 16u, Agp + q * 4);
        CP_ASYNC16(sB[0] + rowoff + q * 16u, Bgp + q * 4);
    }
    CP_COMMIT();
    CP_WAIT0();
    __syncthreads();

    for (int kb = 0; kb < nk; kb++) {
        const int buf = kb & 1;
        if (kb + 1 < nk) {
            const float* ap = Agp + (size_t)(kb + 1) * 32;
            const float* bp = Bgp + (size_t)(kb + 1) * 32;
            #pragma unroll
            for (int q = 0; q < 4; q++) {
                CP_ASYNC16(sA[buf ^ 1] + rowoff + q * 16u, ap + q * 4);
                CP_ASYNC16(sB[buf ^ 1] + rowoff + q * 16u, bp + q * 4);
            }
            CP_COMMIT();
        }

        const uint32_t* Ab = (const uint32_t*)(As + buf * SM_TILE);
        const uint32_t* Bb = (const uint32_t*)(Bs + buf * SM_TILE);

        #pragma unroll
        for (int ks = 0; ks < 4; ks++) {
            const int k0 = ks * 8;
            uint32_t af[4][4], bf[4][2];
            #pragma unroll
            for (int mt = 0; mt < 4; mt++) {
                const uint32_t* base = Ab + (wm * 64 + mt * 16 + g) * SM_STRIDE + k0 + tq;
                af[mt][0] = base[0];
                af[mt][1] = base[8 * SM_STRIDE];
                af[mt][2] = base[4];
                af[mt][3] = base[8 * SM_STRIDE + 4];
            }
            #pragma unroll
            for (int nt = 0; nt < 4; nt++) {
                const uint32_t* base = Bb + (wn * 32 + nt * 8 + g) * SM_STRIDE + k0 + tq;
                bf[nt][0] = base[0];
                bf[nt][1] = base[4];
            }
            #pragma unroll
            for (int mt = 0; mt < 4; mt++)
                #pragma unroll
                for (int nt = 0; nt < 4; nt++)
                    mma_tf32(acc[mt][nt][0], acc[mt][nt][1], acc[mt][nt][2], acc[mt][nt][3],
                             af[mt][0], af[mt][1], af[mt][2], af[mt][3],
                             bf[nt][0], bf[nt][1]);
        }

        if (kb + 1 < nk) {
            CP_WAIT0();
            __syncthreads();
        }
    }

    const bool vec_ok = ((ldc & 1) == 0);
    float es[4][2];
    if (CE_SUM) {
        #pragma unroll
        for (int mt = 0; mt < 4; mt++) { es[mt][0] = 0.f; es[mt][1] = 0.f; }
    }
    #pragma unroll
    for (int mt = 0; mt < 4; mt++) {
        #pragma unroll
        for (int nt = 0; nt < 4; nt++) {
            const int mrow0 = m0 + wm * 64 + mt * 16 + g;
            const int ncol  = n0 + wn * 32 + nt * 8 + 2 * tq;
            #pragma unroll
            for (int half = 0; half < 2; half++) {
                const int m = mrow0 + half * 8;
                float v0 = acc[mt][nt][half * 2 + 0];
                float v1 = acc[mt][nt][half * 2 + 1];
                if (HAS_BIAS) { v0 += bias[ncol]; v1 += bias[ncol + 1]; }
                if (DO_GELU)  { v0 = gelu_exact(v0); v1 = gelu_exact(v1); }
                if (HAS_RES) {
                    v0 += R[(size_t)m * ldc + ncol];
                    v1 += R[(size_t)m * ldc + ncol + 1];
                }
                if (ROUND_OUT) { v0 = f2tf32_f(v0); v1 = f2tf32_f(v1); }
                if (CE_SUM) {
                    float e = 0.f;
                    if (ncol < N)     e += __expf(v0);
                    if (ncol + 1 < N) e += __expf(v1);
                    es[mt][half] += e;
                }
                float* cp = C + (size_t)m * ldc + ncol;
                if (vec_ok && (ncol + 1 < N)) {
                    *(float2*)cp = make_float2(v0, v1);
                } else {
                    if (ncol < N)     cp[0] = v0;
                    if (ncol + 1 < N) cp[1] = v1;
                }
            }
        }
    }
    if (CE_SUM) {
        __syncthreads();
        #pragma unroll
        for (int mt = 0; mt < 4; mt++) {
            atomicAdd(&rs[wm * 64 + mt * 16 + g],     es[mt][0]);
            atomicAdd(&rs[wm * 64 + mt * 16 + g + 8], es[mt][1]);
        }
        __syncthreads();
        if (tid < 128) atomicAdd(&rowsum[m0 + tid], rs[tid]);
    }
}

// ---------------- weight transpose [K,N] -> [NPAD,K], tf32-rounded ----------
__global__ void __launch_bounds__(256)
transpose_kernel(const float* __restrict__ in, float* __restrict__ out,
                 int K, int N, int NPAD)
{
    __shared__ float t[32][33];
    const int k0 = blockIdx.x * 32, n0 = blockIdx.y * 32;
    const float* ip = in  + (size_t)blockIdx.z * K * N;
    float* op       = out + (size_t)blockIdx.z * NPAD * K;
    const int x = threadIdx.x & 31, y = threadIdx.x >> 5;
    #pragma unroll
    for (int i = y; i < 32; i += 8) {
        int n = n0 + x;
        t[i][x] = (n < N) ? f2tf32_f(ip[(size_t)(k0 + i) * N + n]) : 0.f;
    }
    __syncthreads();
    #pragma unroll
    for (int i = y; i < 32; i += 8) {
        int n = n0 + i;
        if (n < NPAD) op[(size_t)n * K + k0 + x] = t[x][i];
    }
}

// ---------------- block reduce (used by ce_final) ----------------------------
__device__ __forceinline__ float blockReduceSum(float v) {
    __shared__ float sh[32];
    int lane = threadIdx.x & 31, wid = threadIdx.x >> 5;
    #pragma unroll
    for (int o = 16; o; o >>= 1) v += __shfl_xor_sync(0xffffffffu, v, o);
    if (lane == 0) sh[wid] = v;
    __syncthreads();
    if (wid == 0) {
        v = (lane < (int)(blockDim.x >> 5)) ? sh[lane] : 0.f;
        #pragma unroll
        for (int o = 16; o; o >>= 1) v += __shfl_xor_sync(0xffffffffu, v, o);
        if (lane == 0) sh[0] = v;
    }
    __syncthreads();
    float r = sh[0];
    __syncthreads();
    return r;
}

// ---------------- embedding / LN -------------------------------------------
__global__ void embed_kernel(const int* __restrict__ idx,
                             const float* __restrict__ wte,
                             const float* __restrict__ wpe,
                             float* __restrict__ x) {
    int t = blockIdx.x;
    int pos = t & (S_LEN - 1);
    int tok = idx[t];
    const float* we = wte + (size_t)tok * DMODEL;
    const float* pe = wpe + (size_t)pos * DMODEL;
    float* xr = x + (size_t)t * DMODEL;
    for (int d = threadIdx.x; d < DMODEL; d += blockDim.x)
        xr[d] = we[d] + pe[d];
}

// warp-per-row LN: 8 rows/block, shfl-only reductions, float4 I/O.
__global__ void __launch_bounds__(256) ln_kernel(const float* __restrict__ x,
                                                 const float* __restrict__ w,
                                                 const float* __restrict__ b,
                                                 float* __restrict__ y) {
    const int warp = threadIdx.x >> 5, lane = threadIdx.x & 31;
    const int r = blockIdx.x * 8 + warp;
    const float4* xr = (const float4*)(x + (size_t)r * DMODEL);
    float4 v[6];
    float s = 0.f;
    #pragma unroll
    for (int j = 0; j < 6; j++) {
        v[j] = xr[lane + 32 * j];
        s += v[j].x + v[j].y + v[j].z + v[j].w;
    }
    #pragma unroll
    for (int o = 16; o; o >>= 1) s += __shfl_xor_sync(0xffffffffu, s, o);
    const float mean = s * (1.f / DMODEL);
    float vs = 0.f;
    #pragma unroll
    for (int j = 0; j < 6; j++) {
        float dx = v[j].x - mean, dy = v[j].y - mean, dz = v[j].z - mean, dw = v[j].w - mean;
        vs += dx * dx + dy * dy + dz * dz + dw * dw;
    }
    #pragma unroll
    for (int o = 16; o; o >>= 1) vs += __shfl_xor_sync(0xffffffffu, vs, o);
    const float rstd = rsqrtf(vs * (1.f / DMODEL) + 1e-5f);
    const float4* wv = (const float4*)w;
    const float4* bv = (const float4*)b;
    float4* yr = (float4*)(y + (size_t)r * DMODEL);
    #pragma unroll
    for (int j = 0; j < 6; j++) {
        const int c = lane + 32 * j;
        float4 ww = wv[c], bb = bv[c];
        float4 o4;
        o4.x = f2tf32_f((v[j].x - mean) * rstd * ww.x + bb.x);
        o4.y = f2tf32_f((v[j].y - mean) * rstd * ww.y + bb.y);
        o4.z = f2tf32_f((v[j].z - mean) * rstd * ww.z + bb.z);
        o4.w = f2tf32_f((v[j].w - mean) * rstd * ww.w + bb.w);
        yr[c] = o4;
    }
}

// ---------------- flash attention (fp32, causal; 64-row Q tiles, R15) --------
// One fewer CTA barrier per k-tile: P rows are private to each 16-lane tx
// group, so the post-P-write sync is __syncwarp (V already fenced above).
#define AST 68
#define ATT_SMEM (4 * 64 * AST * 4)

__global__ void __launch_bounds__(256) attn_kernel(const float* __restrict__ qkv,
                                                   float* __restrict__ out) {
    extern __shared__ float smf[];
    float* Qs  = smf;
    float* KsT = Qs  + 64 * AST;
    float* Vs  = KsT + 64 * AST;
    float* Ps  = Vs  + 64 * AST;

    const int b = blockIdx.z, h = blockIdx.y, qt = blockIdx.x;
    const int q0 = qt * 64;
    const int t = threadIdx.x;
    const int tx = t & 15, ty = t >> 4;
    const float scale = 0.125f;

    for (int i = t; i < 64 * 16; i += 256) {
        int r = i >> 4, d4 = (i & 15) * 4;
        float4 q4 = *(const float4*)(qkv + (size_t)(b * S_LEN + q0 + r) * D3 + h * HDIM + d4);
        *(float4*)&Qs[r * AST + d4] = q4;
    }

    float m[4], l[4], o[4][4];
    #pragma unroll
    for (int i = 0; i < 4; i++) {
        m[i] = -3.0e38f; l[i] = 0.f;
        #pragma unroll
        for (int j = 0; j < 4; j++) o[i][j] = 0.f;
    }

    for (int kt = 0; kt <= qt; kt++) {
        int k0r = kt * 64;
        __syncthreads();   // prior Ps/Vs/KsT reads done; covers Q load on kt==0
        for (int i = t; i < 64 * 16; i += 256) {
            int r = i >> 4, d4 = (i & 15) * 4;
            size_t row = (size_t)(b * S_LEN + k0r + r) * D3 + h * HDIM + d4;
            float4 k4 = *(const float4*)(qkv + row + DMODEL);
            float4 v4 = *(const float4*)(qkv + row + 2 * DMODEL);
            KsT[(d4 + 0) * AST + r] = k4.x;
            KsT[(d4 + 1) * AST + r] = k4.y;
            KsT[(d4 + 2) * AST + r] = k4.z;
            KsT[(d4 + 3) * AST + r] = k4.w;
            *(float4*)&Vs[r * AST + d4] = v4;
        }
        __syncthreads();

        float s[4][4];
        #pragma unroll
        for (int i = 0; i < 4; i++)
            #pragma unroll
            for (int j = 0; j < 4; j++) s[i][j] = 0.f;
        for (int d0 = 0; d0 < 64; d0 += 4) {
            float4 qv[4], kv[4];
            #pragma unroll
            for (int i = 0; i < 4; i++) qv[i] = *(float4*)&Qs[(ty * 4 + i) * AST + d0];
            #pragma unroll
            for (int dd = 0; dd < 4; dd++) kv[dd] = *(float4*)&KsT[(d0 + dd) * AST + tx * 4];
            #pragma unroll
            for (int i = 0; i < 4; i++) {
                const float qa[4] = {qv[i].x, qv[i].y, qv[i].z, qv[i].w};
                #pragma unroll
                for (int dd = 0; dd < 4; dd++) {
                    s[i][0] = fmaf(qa[dd], kv[dd].x, s[i][0]);
                    s[i][1] = fmaf(qa[dd], kv[dd].y, s[i][1]);
                    s[i][2] = fmaf(qa[dd], kv[dd].z, s[i][2]);
                    s[i][3] = fmaf(qa[dd], kv[dd].w, s[i][3]);
                }
            }
        }
        #pragma unroll
        for (int i = 0; i < 4; i++)
            #pragma unroll
            for (int j = 0; j < 4; j++) {
                s[i][j] *= scale;
                if (kt == qt && (tx * 4 + j) > (ty * 4 + i)) s[i][j] = -1.0e30f;
            }

        float p[4][4];
        #pragma unroll
        for (int i = 0; i < 4; i++) {
            float mt = fmaxf(fmaxf(s[i][0], s[i][1]), fmaxf(s[i][2], s[i][3]));
            #pragma unroll
            for (int off = 8; off; off >>= 1)
                mt = fmaxf(mt, __shfl_xor_sync(0xffffffffu, mt, off, 16));
            float mn = fmaxf(m[i], mt);
            float alpha = __expf(m[i] - mn);
            float ps = 0.f;
            #pragma unroll
            for (int j = 0; j < 4; j++) { p[i][j] = __expf(s[i][j] - mn); ps += p[i][j]; }
            #pragma unroll
            for (int off = 8; off; off >>= 1)
                ps += __shfl_xor_sync(0xffffffffu, ps, off, 16);
            l[i] = l[i] * alpha + ps;
            m[i] = mn;
            #pragma unroll
            for (int j = 0; j < 4; j++) o[i][j] *= alpha;
        }

        // stage P: rows ty*4.. are written and read only by this warp's lanes
        #pragma unroll
        for (int i = 0; i < 4; i++)
            *(float4*)&Ps[(ty * 4 + i) * AST + tx * 4] = make_float4(p[i][0], p[i][1], p[i][2], p[i][3]);
        __syncwarp();

        for (int k0 = 0; k0 < 64; k0 += 4) {
            float4 pv[4], vv[4];
            #pragma unroll
            for (int i = 0; i < 4; i++) pv[i] = *(float4*)&Ps[(ty * 4 + i) * AST + k0];
            #pragma unroll
            for (int kk = 0; kk < 4; kk++) vv[kk] = *(float4*)&Vs[(k0 + kk) * AST + tx * 4];
            #pragma unroll
            for (int i = 0; i < 4; i++) {
                const float pa[4] = {pv[i].x, pv[i].y, pv[i].z, pv[i].w};
                #pragma unroll
                for (int kk = 0; kk < 4; kk++) {
                    o[i][0] = fmaf(pa[kk], vv[kk].x, o[i][0]);
                    o[i][1] = fmaf(pa[kk], vv[kk].y, o[i][1]);
                    o[i][2] = fmaf(pa[kk], vv[kk].z, o[i][2]);
                    o[i][3] = fmaf(pa[kk], vv[kk].w, o[i][3]);
                }
            }
        }
    }

    #pragma unroll
    for (int i = 0; i < 4; i++) {
        float inv = 1.f / l[i];
        float4 ov = make_float4(f2tf32_f(o[i][0] * inv), f2tf32_f(o[i][1] * inv),
                                f2tf32_f(o[i][2] * inv), f2tf32_f(o[i][3] * inv));
        *(float4*)(out + (size_t)(b * S_LEN + q0 + ty * 4 + i) * DMODEL + h * HDIM + tx * 4) = ov;
    }
}

// ---------------- CE final: loss = mean( log(rowsum) - logit[label] ) -------
__global__ void __launch_bounds__(256) ce_final_kernel(const float* __restrict__ rowsum,
                                                       const float* __restrict__ logits,
                                                       const int* __restrict__ labels,
                                                       float* __restrict__ out) {
    float s = 0.f;
    for (int r = threadIdx.x; r < NTOK; r += 256)
        s += logf(rowsum[r]) - logits[(size_t)r * VOCAB + labels[r]];
    s = blockReduceSum(s);
    if (threadIdx.x == 0) out[0] = s * (1.f / NTOK);
}

// ---------------- host launcher ----------------------------------------------
extern "C" void kernel_launch(void* const* d_in, const int* in_sizes, int n_in,
                              void* d_out, int out_size) {
    const int*   idx   = (const int*)  d_in[0];
    const int*   preds = (const int*)  d_in[1];
    const float* wte   = (const float*)d_in[2];
    const float* wpe   = (const float*)d_in[3];
    const float* ln1w  = (const float*)d_in[4];
    const float* ln1b  = (const float*)d_in[5];
    const float* qkvw  = (const float*)d_in[6];
    const float* qkvb  = (const float*)d_in[7];
    const float* projw = (const float*)d_in[8];
    const float* projb = (const float*)d_in[9];
    const float* ln2w  = (const float*)d_in[10];
    const float* ln2b  = (const float*)d_in[11];
    const float* f1w   = (const float*)d_in[12];
    const float* f1b   = (const float*)d_in[13];
    const float* f2w   = (const float*)d_in[14];
    const float* f2b   = (const float*)d_in[15];
    const float* lnfw  = (const float*)d_in[16];
    const float* lnfb  = (const float*)d_in[17];
    const float* lmw   = (const float*)d_in[18];
    float* out = (float*)d_out;

    float *x, *h, *qkv, *att, *mlp, *rowsum;
    float *qkvwT, *projwT, *f1wT, *f2wT, *lmwT;
    cudaGetSymbolAddress((void**)&x,   g_x);
    cudaGetSymbolAddress((void**)&h,   g_h);
    cudaGetSymbolAddress((void**)&qkv, g_qkv);
    cudaGetSymbolAddress((void**)&att, g_att);
    cudaGetSymbolAddress((void**)&mlp, g_mlp);
    cudaGetSymbolAddress((void**)&rowsum, g_rowsum);
    cudaGetSymbolAddress((void**)&qkvwT, g_qkvwT);
    cudaGetSymbolAddress((void**)&projwT, g_projwT);
    cudaGetSymbolAddress((void**)&f1wT, g_f1wT);
    cudaGetSymbolAddress((void**)&f2wT, g_f2wT);
    cudaGetSymbolAddress((void**)&lmwT, g_lmwT);

    cudaFuncSetAttribute(attn_kernel, cudaFuncAttributeMaxDynamicSharedMemorySize, ATT_SMEM);
    cudaFuncSetAttribute(mma_gemm<true, false, false, false, false>, cudaFuncAttributeMaxDynamicSharedMemorySize, GEMM_SMEM);
    cudaFuncSetAttribute(mma_gemm<true, false, true,  false, false>, cudaFuncAttributeMaxDynamicSharedMemorySize, GEMM_SMEM);
    cudaFuncSetAttribute(mma_gemm<true, true,  false, true,  false>, cudaFuncAttributeMaxDynamicSharedMemorySize, GEMM_SMEM);
    cudaFuncSetAttribute(mma_gemm<false, false, false, false, true>, cudaFuncAttributeMaxDynamicSharedMemorySize, GEMM_SMEM);

    // Launch order keeps the first mma_gemm at launch index 3 (ncu -s window).
    transpose_kernel<<<dim3(DMODEL / 32, D3 / 32, NLAYER), 256>>>(qkvw, qkvwT, DMODEL, D3, D3);
    embed_kernel<<<NTOK, 256>>>(idx, wte, wpe, x);
    ln_kernel<<<NTOK / 8, 256>>>(x, ln1w, ln1b, h);
    mma_gemm<true, false, false, false, false><<<dim3(NTOK / 128, D3 / 128), 256, GEMM_SMEM>>>(
        h, qkvwT, qkvb, nullptr, qkv, NTOK, D3, DMODEL, D3, nullptr);

    transpose_kernel<<<dim3(DMODEL / 32, DMODEL / 32, NLAYER), 256>>>(projw, projwT, DMODEL, DMODEL, DMODEL);
    transpose_kernel<<<dim3(DMODEL / 32, DFF / 32, NLAYER), 256>>>(f1w, f1wT, DMODEL, DFF, DFF);
    transpose_kernel<<<dim3(DFF / 32, DMODEL / 32, NLAYER), 256>>>(f2w, f2wT, DFF, DMODEL, DMODEL);
    transpose_kernel<<<dim3(DMODEL / 32, VPAD / 32, 1), 256>>>(lmw, lmwT, DMODEL, VOCAB, VPAD);
    cudaMemsetAsync(rowsum, 0, NTOK * sizeof(float));

    for (int l = 0; l < NLAYER; l++) {
        if (l > 0) {
            ln_kernel<<<NTOK / 8, 256>>>(x, ln1w + (size_t)l * DMODEL, ln1b + (size_t)l * DMODEL, h);
            mma_gemm<true, false, false, false, false><<<dim3(NTOK / 128, D3 / 128), 256, GEMM_SMEM>>>(
                h, qkvwT + (size_t)l * D3 * DMODEL, qkvb + (size_t)l * D3,
                nullptr, qkv, NTOK, D3, DMODEL, D3, nullptr);
        }

        attn_kernel<<<dim3(S_LEN / 64, NHEAD, BATCH), 256, ATT_SMEM>>>(qkv, att);

        mma_gemm<true, false, true, false, false><<<dim3(NTOK / 128, DMODEL / 128), 256, GEMM_SMEM>>>(
            att, projwT + (size_t)l * DMODEL * DMODEL, projb + (size_t)l * DMODEL,
            x, x, NTOK, DMODEL, DMODEL, DMODEL, nullptr);

        ln_kernel<<<NTOK / 8, 256>>>(x, ln2w + (size_t)l * DMODEL, ln2b + (size_t)l * DMODEL, h);

        mma_gemm<true, true, false, true, false><<<dim3(NTOK / 128, DFF / 128), 256, GEMM_SMEM>>>(
            h, f1wT + (size_t)l * DFF * DMODEL, f1b + (size_t)l * DFF,
            nullptr, mlp, NTOK, DFF, DMODEL, DFF, nullptr);

        mma_gemm<true, false, true, false, false><<<dim3(NTOK / 128, DMODEL / 128), 256, GEMM_SMEM>>>(
            mlp, f2wT + (size_t)l * DMODEL * DFF, f2b + (size_t)l * DMODEL,
            x, x, NTOK, DMODEL, DFF, DMODEL, nullptr);
    }

    ln_kernel<<<NTOK / 8, 256>>>(x, lnfw, lnfb, h);

    mma_gemm<false, false, false, false, true><<<dim3(NTOK / 128, VPAD / 128), 256, GEMM_SMEM>>>(
        h, lmwT, nullptr, nullptr, out, NTOK, VOCAB, DMODEL, VOCAB, rowsum);

    ce_final_kernel<<<1, 256>>>(rowsum, out, preds, out + (size_t)NTOK * VOCAB);
}